// round 17
// baseline (speedup 1.0000x reference)
#include <cuda_runtime.h>

#define NB 32      // batch
#define NA 286     // atoms
#define CIN 23
#define HH 100     // hidden width of radial MLP
#define BPAD 288   // padded atom count
#define NODES 256  // r-table nodes over [0, RMAX]
#define RMAX 4.5f  // all basis functions are exactly 0 at r >= 4.5

// ---------------- device scratch ----------------
__device__ float  g_V[HH][NODES];         // V[k][ir] = relu(h_k(r_ir))
__device__ float  g_T[NB][BPAD][NODES];   // T[z][b][ir] = sum_k V[k][ir] * g[z][k][b]  (9.4 MB)
__device__ float  g_cz[NB];
__device__ float4 g_geom4[NB][BPAD];      // (x,y,z,0), zero-padded
__device__ float  g_feats[NB][NA];

// ---------------- aux: geom4 + cz (one block per z) ----------------
__global__ void __launch_bounds__(256) k_aux(const float* __restrict__ features,
                                             const float* __restrict__ geometry,
                                             const float* __restrict__ rb2) {
    const int z = blockIdx.x;
    const int tid = threadIdx.x;

    for (int b = tid; b < BPAD; b += 256) {
        float4 v = make_float4(0.f, 0.f, 0.f, 0.f);
        if (b < NA) {
            const float* p = geometry + (z * NA + b) * 3;
            v.x = p[0]; v.y = p[1]; v.z = p[2];
        }
        g_geom4[z][b] = v;
    }
    __shared__ float red[256];
    float s = 0.f;
    const int TOT = NA * CIN;
    for (int i = tid; i < TOT; i += 256)
        s = fmaf(rb2[i % CIN], features[z * TOT + i], s);
    red[tid] = s;
    __syncthreads();
    for (int off = 128; off; off >>= 1) {
        if (tid < off) red[tid] += red[tid + off];
        __syncthreads();
    }
    if (tid == 0) g_cz[z] = red[0];
}

// ---------------- basis: cos(pi/2 * t) via even poly ----------------
__device__ __forceinline__ float cospi_half(float t) {
    float y = t * t;
    float p = fmaf(9.1926027e-4f, y, -2.0863481e-2f);
    p = fmaf(p, y,  2.5366951e-1f);
    p = fmaf(p, y, -1.2337006f);
    p = fmaf(p, y,  1.0f);
    return p;
}
__device__ __forceinline__ void basis3(float r, float& p0, float& p1, float& p2) {
    const float inv = 1.0f / 1.5f;
    float zz = r * inv;
    float t0 = 1.f - fmaxf(2.f - fmaxf(zz + 1.f, 0.f), 0.f);
    float t1 = 1.f - fmaxf(2.f - fmaxf(zz,       0.f), 0.f);
    float t2 = 1.f - fmaxf(2.f - fmaxf(zz - 1.f, 0.f), 0.f);
    p0 = cospi_half(t0);
    p1 = cospi_half(t1);
    p2 = cospi_half(t2);
}

// ---------------- V build: V[k][ir] = relu(h_k(r_ir)) ----------------
__global__ void __launch_bounds__(NODES) k_vbuild(const float* __restrict__ rW1,
                                                  const float* __restrict__ rb1) {
    const int k  = blockIdx.x;
    const int ir = threadIdx.x;
    const float DELTA = RMAX / (float)(NODES - 1);
    float r = ir * DELTA;
    float p0, p1, p2;
    basis3(r, p0, p1, p2);
    float h = fmaf(rW1[k], p0, fmaf(rW1[HH + k], p1, fmaf(rW1[2 * HH + k], p2, rb1[k])));
    g_V[k][ir] = fmaxf(h, 0.f);
}

// ---------------- fused table GEMM ----------------
// T[z][b][ir] = sum_k (sum_j rW2[k,j]*features[z,b,j]) * V[k][ir]
// grid (6 b-tiles of 48, 2 ir-tiles of 128, NB). 256 thr; micro-tile 3b x 8ir.
// G computed in-smem from features+rW2 per 50-k chunk.
// ALL smem arrays force-aligned 16B (Vs is float4-read; w2s padded to even 16B size).
__global__ void __launch_bounds__(256) k_tab(const float* __restrict__ features,
                                             const float* __restrict__ rW2) {
    const int z   = blockIdx.z;
    const int b0  = blockIdx.x * 48;
    const int ir0 = blockIdx.y * 128;
    const int tid = threadIdx.x;

    __shared__ __align__(16) float Vs[50][128];   // float4-accessed: declare first + aligned
    __shared__ __align__(16) float Gs[50][48];
    __shared__ __align__(16) float fs[48][25];    // stride 25 (conflict-free), 4800 B
    __shared__ __align__(16) float w2s[50][26];   // stride 26, 5200 B (16B multiple)

    // features tile: loaded once, reused by both k-chunks
    for (int i = tid; i < 48 * CIN; i += 256) {
        int b = i / CIN, j = i % CIN;
        int gb = b0 + b;
        fs[b][j] = (gb < NA) ? features[(z * NA + gb) * CIN + j] : 0.f;
    }

    const int bl = (tid >> 4) * 3;      // 0..45
    const int il = (tid & 15) * 8;      // 0..120

    float acc[3][8];
    #pragma unroll
    for (int j = 0; j < 3; j++)
        #pragma unroll
        for (int q = 0; q < 8; q++) acc[j][q] = 0.f;

    #pragma unroll
    for (int chunk = 0; chunk < 2; chunk++) {
        const int kb = chunk * 50;
        __syncthreads();   // fs ready (1st pass) / prior Gs,Vs consumed
        for (int i = tid; i < 50 * CIN; i += 256)
            w2s[i / CIN][i % CIN] = rW2[(kb + i / CIN) * CIN + i % CIN];
        for (int i = tid; i < 50 * 128; i += 256)
            Vs[i >> 7][i & 127] = g_V[kb + (i >> 7)][ir0 + (i & 127)];
        __syncthreads();

        // Gs[k][b] = <w2s[k], fs[b]>
        for (int i = tid; i < 50 * 48; i += 256) {
            int k = i / 48, b = i % 48;
            float s = 0.f;
            #pragma unroll
            for (int j = 0; j < CIN; j++) s = fmaf(w2s[k][j], fs[b][j], s);
            Gs[k][b] = s;
        }
        __syncthreads();

        #pragma unroll 5
        for (int k = 0; k < 50; k++) {
            float4 v0 = *(const float4*)&Vs[k][il];
            float4 v1 = *(const float4*)&Vs[k][il + 4];
            float gb0 = Gs[k][bl], gb1 = Gs[k][bl + 1], gb2 = Gs[k][bl + 2];
            float vv[8] = {v0.x, v0.y, v0.z, v0.w, v1.x, v1.y, v1.z, v1.w};
            #pragma unroll
            for (int q = 0; q < 8; q++) {
                acc[0][q] = fmaf(gb0, vv[q], acc[0][q]);
                acc[1][q] = fmaf(gb1, vv[q], acc[1][q]);
                acc[2][q] = fmaf(gb2, vv[q], acc[2][q]);
            }
        }
    }

    #pragma unroll
    for (int j = 0; j < 3; j++) {
        float* dst = &g_T[z][b0 + bl + j][ir0 + il];
        *(float4*)dst       = make_float4(acc[j][0], acc[j][1], acc[j][2], acc[j][3]);
        *(float4*)(dst + 4) = make_float4(acc[j][4], acc[j][5], acc[j][6], acc[j][7]);
    }
}

// ---------------- pair kernel: r -> table lerp -> accumulate over b ----------------
// grid (18, NB), 256 thr = 8 warps, warp handles 2 a's; lane = b within 32-tile.
__global__ void __launch_bounds__(256) k_pairs() {
    const int z    = blockIdx.y;
    const int warp = threadIdx.x >> 5;
    const int lane = threadIdx.x & 31;
    const int a0   = blockIdx.x * 16 + warp * 2;
    const float INV = (float)(NODES - 1) / RMAX;
    const float XMAX = (float)(NODES - 2) + 0.999f;   // 254.999

    float ax[2], ay[2], az[2];
    #pragma unroll
    for (int u = 0; u < 2; u++) {
        int a = a0 + u; if (a > NA - 1) a = NA - 1;   // clamp; extras never written
        float4 p = g_geom4[z][a];
        ax[u] = p.x; ay[u] = p.y; az[u] = p.z;
    }

    float acc[2] = {0.f, 0.f};

    #pragma unroll 3
    for (int bt = 0; bt < BPAD; bt += 32) {
        const int b = bt + lane;
        const float4 bg = g_geom4[z][b];
        const float* __restrict__ Tb = g_T[z][b];   // padded b rows are all-zero
        #pragma unroll
        for (int u = 0; u < 2; u++) {
            float dx = bg.x - ax[u], dy = bg.y - ay[u], dz = bg.z - az[u];
            float r = sqrtf(fmaf(dx, dx, fmaf(dy, dy, fmaf(dz, dz, 1e-12f))));
            float x = fminf(r * INV, XMAX);
            int i0 = (int)x;
            float f = x - (float)i0;
            float t0 = __ldg(&Tb[i0]);
            float t1 = __ldg(&Tb[i0 + 1]);
            acc[u] = fmaf(f, t1 - t0, acc[u] + t0);
        }
    }

    #pragma unroll
    for (int u = 0; u < 2; u++) {
        #pragma unroll
        for (int off = 16; off; off >>= 1)
            acc[u] += __shfl_xor_sync(0xffffffffu, acc[u], off);
    }

    if (lane == 0) {
        const float SCALE0 = 0.28209479177387814f / 16.911534525287763f;  // Y0 / sqrt(286)
        float czs = g_cz[z];
        #pragma unroll
        for (int u = 0; u < 2; u++) {
            int a = a0 + u;
            if (a < NA) g_feats[z][a] = (acc[u] + czs) * SCALE0;
        }
    }
}

// ---------------- head MLP: 286 -> 30 -> 10 -> 1 ----------------
__global__ void __launch_bounds__(256) k_head(const float* __restrict__ fc1W,
                                              const float* __restrict__ fc1b,
                                              const float* __restrict__ fc2W,
                                              const float* __restrict__ fc2b,
                                              const float* __restrict__ fc3W,
                                              const float* __restrict__ fc3b,
                                              float* __restrict__ out) {
    const int z = blockIdx.x;
    const int tid = threadIdx.x;
    const int warp = tid >> 5;
    const int lane = tid & 31;
    __shared__ float fsh[BPAD];
    __shared__ float h1[30];
    __shared__ float h2[10];

    for (int i = tid; i < BPAD; i += 256) fsh[i] = (i < NA) ? g_feats[z][i] : 0.f;
    __syncthreads();

    for (int o = warp; o < 30; o += 8) {
        float w[9], f[9];
        #pragma unroll
        for (int kk = 0; kk < 9; kk++) {
            int idx = lane + 32 * kk;
            w[kk] = (idx < NA) ? __ldg(&fc1W[idx * 30 + o]) : 0.f;
            f[kk] = fsh[idx];
        }
        float ssum = 0.f;
        #pragma unroll
        for (int kk = 0; kk < 9; kk++) ssum = fmaf(w[kk], f[kk], ssum);
        #pragma unroll
        for (int off = 16; off; off >>= 1) ssum += __shfl_xor_sync(0xffffffffu, ssum, off);
        if (lane == 0) h1[o] = fmaxf(ssum + fc1b[o], 0.f);
    }
    __syncthreads();

    if (tid < 10) {
        float s = fc2b[tid];
        #pragma unroll
        for (int o = 0; o < 30; o++) s = fmaf(h1[o], fc2W[o * 10 + tid], s);
        h2[tid] = fmaxf(s, 0.f);
    }
    __syncthreads();

    if (tid == 0) {
        float s = fc3b[0];
        #pragma unroll
        for (int p = 0; p < 10; p++) s = fmaf(h2[p], fc3W[p], s);
        out[z] = s;
    }
}

// ---------------- launch ----------------
extern "C" void kernel_launch(void* const* d_in, const int* in_sizes, int n_in,
                              void* d_out, int out_size) {
    const float* features = (const float*)d_in[1];
    const float* geometry = (const float*)d_in[2];
    const float* rW1      = (const float*)d_in[3];
    const float* rb1      = (const float*)d_in[4];
    const float* rW2      = (const float*)d_in[5];
    const float* rb2      = (const float*)d_in[6];
    const float* fc1W     = (const float*)d_in[7];
    const float* fc1b     = (const float*)d_in[8];
    const float* fc2W     = (const float*)d_in[9];
    const float* fc2b     = (const float*)d_in[10];
    const float* fc3W     = (const float*)d_in[11];
    const float* fc3b     = (const float*)d_in[12];
    float* out = (float*)d_out;

    k_aux   <<<NB, 256>>>(features, geometry, rb2);
    k_vbuild<<<HH, NODES>>>(rW1, rb1);
    k_tab   <<<dim3(6, 2, NB), 256>>>(features, rW2);
    k_pairs <<<dim3(18, NB), 256>>>();
    k_head  <<<NB, 256>>>(fc1W, fc1b, fc2W, fc2b, fc3W, fc3b, out);
}